// round 10
// baseline (speedup 1.0000x reference)
#include <cuda_runtime.h>
#include <cuda_bf16.h>
#include <math.h>
#include <stdint.h>

// Problem dims
#define BB 2
#define SS 2048
#define EE 1024
#define HH 16
#define DD 64
#define MM (BB * SS)      // 4096
#define NQKV (3 * EE)     // 3072
#define NROWS (BB * HH * SS)   // 65536 attn_w rows

// ---------------- scratch ----------------
__device__ float g_q[BB * HH * SS * DD];   // [B,H,S,D]
__device__ float g_k[BB * HH * SS * DD];
__device__ float g_v[BB * HH * SS * DD];
__device__ float g_l[NROWS];               // row sums of exp(s)
// pre-split bf16 operands
__device__ __nv_bfloat16 g_xh[MM * EE],  g_xl[MM * EE];      // hidden_states
__device__ __nv_bfloat16 g_wh[EE * NQKV], g_wl[EE * NQKV];   // c_attn_w
__device__ __nv_bfloat16 g_ph[EE * EE],  g_pl[EE * EE];      // c_proj_w
__device__ __nv_bfloat16 g_ctxh[MM * EE], g_ctxl[MM * EE];   // attention context

// ---------------- bf16 helpers ----------------
__device__ __forceinline__ void mma_bf16(float* c, const uint32_t* a, const uint32_t* b) {
    asm volatile(
        "mma.sync.aligned.m16n8k16.row.col.f32.bf16.bf16.f32 "
        "{%0,%1,%2,%3}, {%4,%5,%6,%7}, {%8,%9}, {%0,%1,%2,%3};"
        : "+f"(c[0]), "+f"(c[1]), "+f"(c[2]), "+f"(c[3])
        : "r"(a[0]), "r"(a[1]), "r"(a[2]), "r"(a[3]), "r"(b[0]), "r"(b[1]));
}

__device__ __forceinline__ void ldsm4(uint32_t& r0, uint32_t& r1, uint32_t& r2, uint32_t& r3,
                                      const void* p) {
    uint32_t a = (uint32_t)__cvta_generic_to_shared(p);
    asm volatile("ldmatrix.sync.aligned.m8n8.x4.shared.b16 {%0,%1,%2,%3}, [%4];"
                 : "=r"(r0), "=r"(r1), "=r"(r2), "=r"(r3) : "r"(a));
}

__device__ __forceinline__ void ldsm2t(uint32_t& r0, uint32_t& r1, const void* p) {
    uint32_t a = (uint32_t)__cvta_generic_to_shared(p);
    asm volatile("ldmatrix.sync.aligned.m8n8.x2.trans.shared.b16 {%0,%1}, [%2];"
                 : "=r"(r0), "=r"(r1) : "r"(a));
}

__device__ __forceinline__ void split2(float a, float b, uint32_t& h, uint32_t& l) {
    __nv_bfloat162 th, tl;
    th.x = __float2bfloat16_rn(a);
    th.y = __float2bfloat16_rn(b);
    tl.x = __float2bfloat16_rn(a - __bfloat162float(th.x));
    tl.y = __float2bfloat16_rn(b - __bfloat162float(th.y));
    h = *(uint32_t*)&th;
    l = *(uint32_t*)&tl;
}

// =================================================================================
// Kernel 0: split fp32 array into bf16 hi/lo
// =================================================================================
__global__ __launch_bounds__(256) void split_kernel(
    const float* __restrict__ src, __nv_bfloat16* __restrict__ h,
    __nv_bfloat16* __restrict__ l, int n4)
{
    int i = blockIdx.x * 256 + threadIdx.x;
    if (i >= n4) return;
    float4 v = ((const float4*)src)[i];
    uint32_t h01, h23, l01, l23;
    split2(v.x, v.y, h01, l01);
    split2(v.z, v.w, h23, l23);
    *(uint2*)(h + (size_t)i * 4) = make_uint2(h01, h23);
    *(uint2*)(l + (size_t)i * 4) = make_uint2(l01, l23);
}

#define AP 24
#define BP 136

// =================================================================================
// Kernel 1: QKV GEMM, bf16 3-term, pre-split operands
// =================================================================================
__global__ __launch_bounds__(256, 2) void qkv_gemm_bf16(
    const float* __restrict__ bias)
{
    __shared__ __nv_bfloat16 Ah[128 * AP], Al[128 * AP];
    __shared__ __nv_bfloat16 Bh[16 * BP],  Bl[16 * BP];

    const int bn = blockIdx.x, bm = blockIdx.y;
    const int tid = threadIdx.x;
    const int warp = tid >> 5, lane = tid & 31;
    const int g = lane >> 2, tg = lane & 3;
    const int wm = (warp >> 2) * 64, wn = (warp & 3) * 32;
    const int row0 = bm * 128, col0 = bn * 128;

    const int ar = tid >> 1, ac = (tid & 1) << 3;
    const int bk = tid >> 4, bc = (tid & 15) << 3;

    float C[4][4][4];
#pragma unroll
    for (int mi = 0; mi < 4; mi++)
#pragma unroll
        for (int ni = 0; ni < 4; ni++)
#pragma unroll
            for (int t = 0; t < 4; t++) C[mi][ni][t] = 0.f;

    for (int k0 = 0; k0 < EE; k0 += 16) {
        *(uint4*)&Ah[ar * AP + ac] = *(const uint4*)(g_xh + (size_t)(row0 + ar) * EE + k0 + ac);
        *(uint4*)&Al[ar * AP + ac] = *(const uint4*)(g_xl + (size_t)(row0 + ar) * EE + k0 + ac);
        *(uint4*)&Bh[bk * BP + bc] = *(const uint4*)(g_wh + (size_t)(k0 + bk) * NQKV + col0 + bc);
        *(uint4*)&Bl[bk * BP + bc] = *(const uint4*)(g_wl + (size_t)(k0 + bk) * NQKV + col0 + bc);
        __syncthreads();

        uint32_t a_h[4][4], a_l[4][4], b_h[4][2], b_l[4][2];
#pragma unroll
        for (int mi = 0; mi < 4; mi++) {
            int row = wm + mi * 16 + (lane & 15);
            int ko = (lane >> 4) << 3;
            ldsm4(a_h[mi][0], a_h[mi][1], a_h[mi][2], a_h[mi][3], &Ah[row * AP + ko]);
            ldsm4(a_l[mi][0], a_l[mi][1], a_l[mi][2], a_l[mi][3], &Al[row * AP + ko]);
        }
#pragma unroll
        for (int ni = 0; ni < 4; ni++) {
            int kr = (lane & 7) + (lane & 8);
            int nc = wn + ni * 8;
            ldsm2t(b_h[ni][0], b_h[ni][1], &Bh[kr * BP + nc]);
            ldsm2t(b_l[ni][0], b_l[ni][1], &Bl[kr * BP + nc]);
        }
#pragma unroll
        for (int mi = 0; mi < 4; mi++)
#pragma unroll
            for (int ni = 0; ni < 4; ni++) {
                mma_bf16(C[mi][ni], a_h[mi], b_h[ni]);
                mma_bf16(C[mi][ni], a_h[mi], b_l[ni]);
                mma_bf16(C[mi][ni], a_l[mi], b_h[ni]);
            }
        __syncthreads();
    }

#pragma unroll
    for (int mi = 0; mi < 4; mi++) {
#pragma unroll
        for (int half = 0; half < 2; half++) {
            int r = row0 + wm + mi * 16 + g + half * 8;
            int b_ = r >> 11, s = r & 2047;
#pragma unroll
            for (int ni = 0; ni < 4; ni++) {
#pragma unroll
                for (int c01 = 0; c01 < 2; c01++) {
                    int n = col0 + wn + ni * 8 + 2 * tg + c01;
                    float v = C[mi][ni][half * 2 + c01] + bias[n];
                    int which = n >> 10;
                    int e = n & 1023;
                    int hh = e >> 6, d = e & 63;
                    float* dst = (which == 0) ? g_q : (which == 1) ? g_k : g_v;
                    dst[(size_t)(((b_ * HH) + hh) * SS + s) * DD + d] = v;
                }
            }
        }
    }
}

// =================================================================================
// Kernel 2: single-pass causal attention (R8 core; epilogue emits split ctx)
// =================================================================================
#define QP 72
#define KP 72
#define VP 72
#define PP 72
#define OQH 0
#define OQL (OQH + 128 * QP * 2)
#define OKH (OQL + 128 * QP * 2)
#define OKL (OKH + 64 * KP * 2)
#define OVH (OKL + 64 * KP * 2)
#define OVL (OVH + 64 * VP * 2)
#define OPH (OVL + 64 * VP * 2)
#define OPL (OPH + 128 * PP * 2)
#define ATT_SMEM (OPL + 128 * PP * 2)   // 110592

__global__ __launch_bounds__(256, 2) void attn_kernel(float* __restrict__ attn_w)
{
    extern __shared__ char smraw[];
    __nv_bfloat16* Qh = (__nv_bfloat16*)(smraw + OQH);
    __nv_bfloat16* Ql = (__nv_bfloat16*)(smraw + OQL);
    __nv_bfloat16* Kh = (__nv_bfloat16*)(smraw + OKH);
    __nv_bfloat16* Kl = (__nv_bfloat16*)(smraw + OKL);
    __nv_bfloat16* Vh = (__nv_bfloat16*)(smraw + OVH);
    __nv_bfloat16* Vl = (__nv_bfloat16*)(smraw + OVL);
    __nv_bfloat16* Ph = (__nv_bfloat16*)(smraw + OPH);
    __nv_bfloat16* Pl = (__nv_bfloat16*)(smraw + OPL);

    const int qb = (int)gridDim.x - 1 - (int)blockIdx.x;
    const int h = blockIdx.y, b = blockIdx.z;
    const int tid = threadIdx.x;
    const int warp = tid >> 5, lane = tid & 31;
    const int g = lane >> 2, tg = lane & 3;

    const float* Qg = g_q + ((size_t)(b * HH + h) * SS + qb * 128) * DD;
    const float* Kg = g_k + (size_t)(b * HH + h) * SS * DD;
    const float* Vg = g_v + (size_t)(b * HH + h) * SS * DD;

#pragma unroll
    for (int it = 0; it < 8; it++) {
        int f4 = tid + it * 256;
        int r = f4 >> 4, c = (f4 & 15) << 2;
        float4 v = *(const float4*)(Qg + r * 64 + c);
        uint32_t h01, h23, l01, l23;
        split2(v.x * 0.125f, v.y * 0.125f, h01, l01);
        split2(v.z * 0.125f, v.w * 0.125f, h23, l23);
        *(uint2*)&Qh[r * QP + c] = make_uint2(h01, h23);
        *(uint2*)&Ql[r * QP + c] = make_uint2(l01, l23);
    }
    __syncthreads();

    uint32_t qa_h[4][4], qa_l[4][4];
    {
        int row = warp * 16 + g;
#pragma unroll
        for (int ks = 0; ks < 4; ks++) {
            int d0 = ks * 16 + 2 * tg;
            qa_h[ks][0] = *(uint32_t*)&Qh[row * QP + d0];
            qa_h[ks][1] = *(uint32_t*)&Qh[(row + 8) * QP + d0];
            qa_h[ks][2] = *(uint32_t*)&Qh[row * QP + d0 + 8];
            qa_h[ks][3] = *(uint32_t*)&Qh[(row + 8) * QP + d0 + 8];
            qa_l[ks][0] = *(uint32_t*)&Ql[row * QP + d0];
            qa_l[ks][1] = *(uint32_t*)&Ql[(row + 8) * QP + d0];
            qa_l[ks][2] = *(uint32_t*)&Ql[row * QP + d0 + 8];
            qa_l[ks][3] = *(uint32_t*)&Ql[(row + 8) * QP + d0 + 8];
        }
    }

    float accO[8][4];
#pragma unroll
    for (int dt = 0; dt < 8; dt++)
#pragma unroll
        for (int t = 0; t < 4; t++) accO[dt][t] = 0.f;
    float l0 = 0.f, l1 = 0.f;

    const int rowL = warp * 16 + g;
    const int row0g = qb * 128 + rowL;
    const size_t wbase = (size_t)(b * HH + h) * SS * SS;
    const int nch = 2 * (qb + 1);

    for (int ch = 0; ch < nch; ch++) {
        __syncthreads();
#pragma unroll
        for (int it = 0; it < 4; it++) {
            int f4 = tid + it * 256;
            int key = f4 >> 4, c = (f4 & 15) << 2;
            float4 kv = *(const float4*)(Kg + (size_t)(ch * 64 + key) * 64 + c);
            uint32_t h01, h23, l01, l23;
            split2(kv.x, kv.y, h01, l01); split2(kv.z, kv.w, h23, l23);
            *(uint2*)&Kh[key * KP + c] = make_uint2(h01, h23);
            *(uint2*)&Kl[key * KP + c] = make_uint2(l01, l23);

            float4 vv = *(const float4*)(Vg + (size_t)(ch * 64 + key) * 64 + c);
            float vs[4] = {vv.x, vv.y, vv.z, vv.w};
#pragma unroll
            for (int j = 0; j < 4; j++) {
                __nv_bfloat16 hb = __float2bfloat16_rn(vs[j]);
                Vh[(c + j) * VP + key] = hb;
                Vl[(c + j) * VP + key] = __float2bfloat16_rn(vs[j] - __bfloat162float(hb));
            }
        }
        __syncthreads();

        const bool masked = (ch >= 2 * qb);

#pragma unroll 1
        for (int grp = 0; grp < 2; grp++) {
            float acc[4][4];
#pragma unroll
            for (int q = 0; q < 4; q++)
#pragma unroll
                for (int t = 0; t < 4; t++) acc[q][t] = 0.f;

#pragma unroll
            for (int ks = 0; ks < 4; ks++) {
                int d0 = ks * 16 + 2 * tg;
#pragma unroll
                for (int q = 0; q < 4; q++) {
                    int key = (grp * 4 + q) * 8 + g;
                    uint32_t bh[2], bl[2];
                    bh[0] = *(uint32_t*)&Kh[key * KP + d0];
                    bh[1] = *(uint32_t*)&Kh[key * KP + d0 + 8];
                    bl[0] = *(uint32_t*)&Kl[key * KP + d0];
                    bl[1] = *(uint32_t*)&Kl[key * KP + d0 + 8];
                    mma_bf16(acc[q], qa_h[ks], bh);
                    mma_bf16(acc[q], qa_h[ks], bl);
                    mma_bf16(acc[q], qa_l[ks], bh);
                }
            }

#pragma unroll
            for (int q = 0; q < 4; q++) {
                int nt = grp * 4 + q;
                int colb = ch * 64 + nt * 8 + 2 * tg;
                float e0, e1, e2, e3;
                if (masked) {
                    e0 = (colb     <= row0g)     ? __expf(acc[q][0]) : 0.f;
                    e1 = (colb + 1 <= row0g)     ? __expf(acc[q][1]) : 0.f;
                    e2 = (colb     <= row0g + 8) ? __expf(acc[q][2]) : 0.f;
                    e3 = (colb + 1 <= row0g + 8) ? __expf(acc[q][3]) : 0.f;
                } else {
                    e0 = __expf(acc[q][0]); e1 = __expf(acc[q][1]);
                    e2 = __expf(acc[q][2]); e3 = __expf(acc[q][3]);
                }
                l0 += e0 + e1; l1 += e2 + e3;
                size_t base = wbase + (size_t)row0g * SS + colb;
                *(float2*)(attn_w + base) = make_float2(e0, e1);
                *(float2*)(attn_w + base + (size_t)8 * SS) = make_float2(e2, e3);
                int pc = nt * 8 + 2 * tg;
                uint32_t ph01, pl01, ph23, pl23;
                split2(e0, e1, ph01, pl01);
                split2(e2, e3, ph23, pl23);
                *(uint32_t*)&Ph[rowL * PP + pc]       = ph01;
                *(uint32_t*)&Pl[rowL * PP + pc]       = pl01;
                *(uint32_t*)&Ph[(rowL + 8) * PP + pc] = ph23;
                *(uint32_t*)&Pl[(rowL + 8) * PP + pc] = pl23;
            }
        }
        __syncwarp();

#pragma unroll 1
        for (int ks = 0; ks < 4; ks++) {
            int k0 = ks * 16 + 2 * tg;
            uint32_t pa_h[4], pa_l[4];
            pa_h[0] = *(uint32_t*)&Ph[rowL * PP + k0];
            pa_h[1] = *(uint32_t*)&Ph[(rowL + 8) * PP + k0];
            pa_h[2] = *(uint32_t*)&Ph[rowL * PP + k0 + 8];
            pa_h[3] = *(uint32_t*)&Ph[(rowL + 8) * PP + k0 + 8];
            pa_l[0] = *(uint32_t*)&Pl[rowL * PP + k0];
            pa_l[1] = *(uint32_t*)&Pl[(rowL + 8) * PP + k0];
            pa_l[2] = *(uint32_t*)&Pl[rowL * PP + k0 + 8];
            pa_l[3] = *(uint32_t*)&Pl[(rowL + 8) * PP + k0 + 8];
#pragma unroll
            for (int dt = 0; dt < 8; dt++) {
                int d = dt * 8 + g;
                uint32_t bh[2], bl[2];
                bh[0] = *(uint32_t*)&Vh[d * VP + k0];
                bh[1] = *(uint32_t*)&Vh[d * VP + k0 + 8];
                bl[0] = *(uint32_t*)&Vl[d * VP + k0];
                bl[1] = *(uint32_t*)&Vl[d * VP + k0 + 8];
                mma_bf16(accO[dt], pa_h, bh);
                mma_bf16(accO[dt], pa_h, bl);
                mma_bf16(accO[dt], pa_l, bh);
            }
        }
    }

#pragma unroll
    for (int o = 1; o < 4; o <<= 1) {
        l0 += __shfl_xor_sync(0xffffffffu, l0, o);
        l1 += __shfl_xor_sync(0xffffffffu, l1, o);
    }
    if (tg == 0) {
        g_l[(size_t)(b * HH + h) * SS + row0g] = l0;
        g_l[(size_t)(b * HH + h) * SS + row0g + 8] = l1;
    }
    float inv0 = 1.f / l0, inv1 = 1.f / l1;

#pragma unroll
    for (int dt = 0; dt < 8; dt++) {
        int col = h * 64 + dt * 8 + 2 * tg;
        uint32_t hh, ll;
        split2(accO[dt][0] * inv0, accO[dt][1] * inv0, hh, ll);
        *(uint32_t*)&g_ctxh[(size_t)(b * SS + row0g) * EE + col] = hh;
        *(uint32_t*)&g_ctxl[(size_t)(b * SS + row0g) * EE + col] = ll;
        split2(accO[dt][2] * inv1, accO[dt][3] * inv1, hh, ll);
        *(uint32_t*)&g_ctxh[(size_t)(b * SS + row0g + 8) * EE + col] = hh;
        *(uint32_t*)&g_ctxl[(size_t)(b * SS + row0g + 8) * EE + col] = ll;
    }
}

// =================================================================================
// Kernel 3: FUSED proj GEMM + attn_w rescale.
// Grid = NROWS + 256 = 65792 blocks. bid % 257 == 0 -> proj (exactly 256 blocks:
// 0, 257, ..., 65535). Else rescale, row = bid - bid/257 - 1 in [0, 65535].
// =================================================================================
__global__ __launch_bounds__(256, 2) void proj_rescale_fused(
    const float* __restrict__ bias, float* __restrict__ out,
    float* __restrict__ attn_w)
{
    __shared__ __nv_bfloat16 Ah[128 * AP], Al[128 * AP];
    __shared__ __nv_bfloat16 Bh[16 * BP],  Bl[16 * BP];

    const int bid = blockIdx.x;
    const int tid = threadIdx.x;

    if (bid % 257 != 0) {
        // ---------------- rescale path (65536 rows) ----------------
        const int row = bid - bid / 257 - 1;       // 0..65535
        const int s = row & (SS - 1);
        const float inv = 1.f / g_l[row];
        const int lim = s + 1;
        float* p = attn_w + (size_t)row * SS;

#pragma unroll
        for (int it = 0; it < 2; it++) {
            int c = (tid + it * 256) << 2;
            float4 t;
            if (c + 3 < lim) {
                t = *(float4*)(p + c);
                t.x *= inv; t.y *= inv; t.z *= inv; t.w *= inv;
            } else if (c < lim) {
                t = *(float4*)(p + c);
                t.x = (c     < lim) ? t.x * inv : 0.f;
                t.y = (c + 1 < lim) ? t.y * inv : 0.f;
                t.z = (c + 2 < lim) ? t.z * inv : 0.f;
                t.w = (c + 3 < lim) ? t.w * inv : 0.f;
            } else {
                t = make_float4(0.f, 0.f, 0.f, 0.f);
            }
            *(float4*)(p + c) = t;
        }
        return;
    }

    // ---------------- proj path (256 blocks) ----------------
    const int pbid = bid / 257;                   // 0..255
    const int bn = pbid & 7, bm = pbid >> 3;      // 8 x 32 tiles
    const int warp = tid >> 5, lane = tid & 31;
    const int g = lane >> 2, tg = lane & 3;
    const int wm = (warp >> 2) * 64, wn = (warp & 3) * 32;
    const int row0 = bm * 128, col0 = bn * 128;

    const int ar = tid >> 1, ac = (tid & 1) << 3;
    const int bk = tid >> 4, bc = (tid & 15) << 3;

    float C[4][4][4];
#pragma unroll
    for (int mi = 0; mi < 4; mi++)
#pragma unroll
        for (int ni = 0; ni < 4; ni++)
#pragma unroll
            for (int t = 0; t < 4; t++) C[mi][ni][t] = 0.f;

    for (int k0 = 0; k0 < EE; k0 += 16) {
        *(uint4*)&Ah[ar * AP + ac] = *(const uint4*)(g_ctxh + (size_t)(row0 + ar) * EE + k0 + ac);
        *(uint4*)&Al[ar * AP + ac] = *(const uint4*)(g_ctxl + (size_t)(row0 + ar) * EE + k0 + ac);
        *(uint4*)&Bh[bk * BP + bc] = *(const uint4*)(g_ph + (size_t)(k0 + bk) * EE + col0 + bc);
        *(uint4*)&Bl[bk * BP + bc] = *(const uint4*)(g_pl + (size_t)(k0 + bk) * EE + col0 + bc);
        __syncthreads();

        uint32_t a_h[4][4], a_l[4][4], b_h[4][2], b_l[4][2];
#pragma unroll
        for (int mi = 0; mi < 4; mi++) {
            int row = wm + mi * 16 + (lane & 15);
            int ko = (lane >> 4) << 3;
            ldsm4(a_h[mi][0], a_h[mi][1], a_h[mi][2], a_h[mi][3], &Ah[row * AP + ko]);
            ldsm4(a_l[mi][0], a_l[mi][1], a_l[mi][2], a_l[mi][3], &Al[row * AP + ko]);
        }
#pragma unroll
        for (int ni = 0; ni < 4; ni++) {
            int kr = (lane & 7) + (lane & 8);
            int nc = wn + ni * 8;
            ldsm2t(b_h[ni][0], b_h[ni][1], &Bh[kr * BP + nc]);
            ldsm2t(b_l[ni][0], b_l[ni][1], &Bl[kr * BP + nc]);
        }
#pragma unroll
        for (int mi = 0; mi < 4; mi++)
#pragma unroll
            for (int ni = 0; ni < 4; ni++) {
                mma_bf16(C[mi][ni], a_h[mi], b_h[ni]);
                mma_bf16(C[mi][ni], a_h[mi], b_l[ni]);
                mma_bf16(C[mi][ni], a_l[mi], b_h[ni]);
            }
        __syncthreads();
    }

#pragma unroll
    for (int mi = 0; mi < 4; mi++) {
#pragma unroll
        for (int half = 0; half < 2; half++) {
            int r = row0 + wm + mi * 16 + g + half * 8;
#pragma unroll
            for (int ni = 0; ni < 4; ni++) {
#pragma unroll
                for (int c01 = 0; c01 < 2; c01++) {
                    int n = col0 + wn + ni * 8 + 2 * tg + c01;
                    out[(size_t)r * EE + n] = C[mi][ni][half * 2 + c01] + bias[n];
                }
            }
        }
    }
}

// =================================================================================
// launch
// =================================================================================
extern "C" void kernel_launch(void* const* d_in, const int* in_sizes, int n_in,
                              void* d_out, int out_size)
{
    const float* hs = (const float*)d_in[0];
    const float* aw = (const float*)d_in[1];
    const float* ab = (const float*)d_in[2];
    const float* pw = (const float*)d_in[3];
    const float* pb = (const float*)d_in[4];

    float* out      = (float*)d_out;
    float* attn_out = out;                       // [2,2048,1024]
    float* attn_w   = out + (size_t)MM * EE;     // [2,16,2048,2048]

    cudaFuncSetAttribute(attn_kernel, cudaFuncAttributeMaxDynamicSharedMemorySize,
                         ATT_SMEM);

    __nv_bfloat16 *xh, *xl, *wh, *wl, *ph, *pl;
    cudaGetSymbolAddress((void**)&xh, g_xh); cudaGetSymbolAddress((void**)&xl, g_xl);
    cudaGetSymbolAddress((void**)&wh, g_wh); cudaGetSymbolAddress((void**)&wl, g_wl);
    cudaGetSymbolAddress((void**)&ph, g_ph); cudaGetSymbolAddress((void**)&pl, g_pl);

    split_kernel<<<(MM * EE / 4 + 255) / 256, 256>>>(hs, xh, xl, MM * EE / 4);
    split_kernel<<<(EE * NQKV / 4 + 255) / 256, 256>>>(aw, wh, wl, EE * NQKV / 4);
    split_kernel<<<(EE * EE / 4 + 255) / 256, 256>>>(pw, ph, pl, EE * EE / 4);

    qkv_gemm_bf16<<<dim3(NQKV / 128, MM / 128), 256>>>(ab);
    attn_kernel<<<dim3(SS / 128, HH, BB), 256, ATT_SMEM>>>(attn_w);
    proj_rescale_fused<<<NROWS + 256, 256>>>(pb, attn_out, attn_w);
}

// round 11
// speedup vs baseline: 1.4767x; 1.4767x over previous
#include <cuda_runtime.h>
#include <cuda_bf16.h>
#include <math.h>
#include <stdint.h>

// Problem dims
#define BB 2
#define SS 2048
#define EE 1024
#define HH 16
#define DD 64
#define MM (BB * SS)      // 4096
#define NQKV (3 * EE)     // 3072
#define NROWS (BB * HH * SS)   // 65536 attn_w rows

// ---------------- scratch ----------------
__device__ float g_q[BB * HH * SS * DD];   // [B,H,S,D]
__device__ float g_k[BB * HH * SS * DD];
__device__ float g_v[BB * HH * SS * DD];
__device__ float g_l[NROWS];               // row sums of exp(s)
// pre-split bf16 operands
__device__ __nv_bfloat16 g_xh[MM * EE],  g_xl[MM * EE];      // hidden_states
__device__ __nv_bfloat16 g_wh[EE * NQKV], g_wl[EE * NQKV];   // c_attn_w
__device__ __nv_bfloat16 g_ph[EE * EE],  g_pl[EE * EE];      // c_proj_w
__device__ __nv_bfloat16 g_ctxh[MM * EE], g_ctxl[MM * EE];   // attention context

// ---------------- bf16 helpers ----------------
__device__ __forceinline__ void mma_bf16(float* c, const uint32_t* a, const uint32_t* b) {
    asm volatile(
        "mma.sync.aligned.m16n8k16.row.col.f32.bf16.bf16.f32 "
        "{%0,%1,%2,%3}, {%4,%5,%6,%7}, {%8,%9}, {%0,%1,%2,%3};"
        : "+f"(c[0]), "+f"(c[1]), "+f"(c[2]), "+f"(c[3])
        : "r"(a[0]), "r"(a[1]), "r"(a[2]), "r"(a[3]), "r"(b[0]), "r"(b[1]));
}

__device__ __forceinline__ void ldsm4(uint32_t& r0, uint32_t& r1, uint32_t& r2, uint32_t& r3,
                                      const void* p) {
    uint32_t a = (uint32_t)__cvta_generic_to_shared(p);
    asm volatile("ldmatrix.sync.aligned.m8n8.x4.shared.b16 {%0,%1,%2,%3}, [%4];"
                 : "=r"(r0), "=r"(r1), "=r"(r2), "=r"(r3) : "r"(a));
}

__device__ __forceinline__ void ldsm2t(uint32_t& r0, uint32_t& r1, const void* p) {
    uint32_t a = (uint32_t)__cvta_generic_to_shared(p);
    asm volatile("ldmatrix.sync.aligned.m8n8.x2.trans.shared.b16 {%0,%1}, [%2];"
                 : "=r"(r0), "=r"(r1) : "r"(a));
}

__device__ __forceinline__ void split2(float a, float b, uint32_t& h, uint32_t& l) {
    __nv_bfloat162 th, tl;
    th.x = __float2bfloat16_rn(a);
    th.y = __float2bfloat16_rn(b);
    tl.x = __float2bfloat16_rn(a - __bfloat162float(th.x));
    tl.y = __float2bfloat16_rn(b - __bfloat162float(th.y));
    h = *(uint32_t*)&th;
    l = *(uint32_t*)&tl;
}

// =================================================================================
// Kernel 0: split fp32 array into bf16 hi/lo
// =================================================================================
__global__ __launch_bounds__(256) void split_kernel(
    const float* __restrict__ src, __nv_bfloat16* __restrict__ h,
    __nv_bfloat16* __restrict__ l, int n4)
{
    int i = blockIdx.x * 256 + threadIdx.x;
    if (i >= n4) return;
    float4 v = ((const float4*)src)[i];
    uint32_t h01, h23, l01, l23;
    split2(v.x, v.y, h01, l01);
    split2(v.z, v.w, h23, l23);
    *(uint2*)(h + (size_t)i * 4) = make_uint2(h01, h23);
    *(uint2*)(l + (size_t)i * 4) = make_uint2(l01, l23);
}

#define AP 24
#define BP 136

// =================================================================================
// Kernel 1: QKV GEMM, bf16 3-term, pre-split operands (R10, known good)
// =================================================================================
__global__ __launch_bounds__(256, 2) void qkv_gemm_bf16(
    const float* __restrict__ bias)
{
    __shared__ __nv_bfloat16 Ah[128 * AP], Al[128 * AP];
    __shared__ __nv_bfloat16 Bh[16 * BP],  Bl[16 * BP];

    const int bn = blockIdx.x, bm = blockIdx.y;
    const int tid = threadIdx.x;
    const int warp = tid >> 5, lane = tid & 31;
    const int g = lane >> 2, tg = lane & 3;
    const int wm = (warp >> 2) * 64, wn = (warp & 3) * 32;
    const int row0 = bm * 128, col0 = bn * 128;

    const int ar = tid >> 1, ac = (tid & 1) << 3;
    const int bk = tid >> 4, bc = (tid & 15) << 3;

    float C[4][4][4];
#pragma unroll
    for (int mi = 0; mi < 4; mi++)
#pragma unroll
        for (int ni = 0; ni < 4; ni++)
#pragma unroll
            for (int t = 0; t < 4; t++) C[mi][ni][t] = 0.f;

    for (int k0 = 0; k0 < EE; k0 += 16) {
        *(uint4*)&Ah[ar * AP + ac] = *(const uint4*)(g_xh + (size_t)(row0 + ar) * EE + k0 + ac);
        *(uint4*)&Al[ar * AP + ac] = *(const uint4*)(g_xl + (size_t)(row0 + ar) * EE + k0 + ac);
        *(uint4*)&Bh[bk * BP + bc] = *(const uint4*)(g_wh + (size_t)(k0 + bk) * NQKV + col0 + bc);
        *(uint4*)&Bl[bk * BP + bc] = *(const uint4*)(g_wl + (size_t)(k0 + bk) * NQKV + col0 + bc);
        __syncthreads();

        uint32_t a_h[4][4], a_l[4][4], b_h[4][2], b_l[4][2];
#pragma unroll
        for (int mi = 0; mi < 4; mi++) {
            int row = wm + mi * 16 + (lane & 15);
            int ko = (lane >> 4) << 3;
            ldsm4(a_h[mi][0], a_h[mi][1], a_h[mi][2], a_h[mi][3], &Ah[row * AP + ko]);
            ldsm4(a_l[mi][0], a_l[mi][1], a_l[mi][2], a_l[mi][3], &Al[row * AP + ko]);
        }
#pragma unroll
        for (int ni = 0; ni < 4; ni++) {
            int kr = (lane & 7) + (lane & 8);
            int nc = wn + ni * 8;
            ldsm2t(b_h[ni][0], b_h[ni][1], &Bh[kr * BP + nc]);
            ldsm2t(b_l[ni][0], b_l[ni][1], &Bl[kr * BP + nc]);
        }
#pragma unroll
        for (int mi = 0; mi < 4; mi++)
#pragma unroll
            for (int ni = 0; ni < 4; ni++) {
                mma_bf16(C[mi][ni], a_h[mi], b_h[ni]);
                mma_bf16(C[mi][ni], a_h[mi], b_l[ni]);
                mma_bf16(C[mi][ni], a_l[mi], b_h[ni]);
            }
        __syncthreads();
    }

#pragma unroll
    for (int mi = 0; mi < 4; mi++) {
#pragma unroll
        for (int half = 0; half < 2; half++) {
            int r = row0 + wm + mi * 16 + g + half * 8;
            int b_ = r >> 11, s = r & 2047;
#pragma unroll
            for (int ni = 0; ni < 4; ni++) {
#pragma unroll
                for (int c01 = 0; c01 < 2; c01++) {
                    int n = col0 + wn + ni * 8 + 2 * tg + c01;
                    float v = C[mi][ni][half * 2 + c01] + bias[n];
                    int which = n >> 10;
                    int e = n & 1023;
                    int hh = e >> 6, d = e & 63;
                    float* dst = (which == 0) ? g_q : (which == 1) ? g_k : g_v;
                    dst[(size_t)(((b_ * HH) + hh) * SS + s) * DD + d] = v;
                }
            }
        }
    }
}

// =================================================================================
// Kernel 2: single-pass causal attention (R8/R10 core, known good)
// =================================================================================
#define QP 72
#define KP 72
#define VP 72
#define PP 72
#define OQH 0
#define OQL (OQH + 128 * QP * 2)
#define OKH (OQL + 128 * QP * 2)
#define OKL (OKH + 64 * KP * 2)
#define OVH (OKL + 64 * KP * 2)
#define OVL (OVH + 64 * VP * 2)
#define OPH (OVL + 64 * VP * 2)
#define OPL (OPH + 128 * PP * 2)
#define ATT_SMEM (OPL + 128 * PP * 2)   // 110592

__global__ __launch_bounds__(256, 2) void attn_kernel(float* __restrict__ attn_w)
{
    extern __shared__ char smraw[];
    __nv_bfloat16* Qh = (__nv_bfloat16*)(smraw + OQH);
    __nv_bfloat16* Ql = (__nv_bfloat16*)(smraw + OQL);
    __nv_bfloat16* Kh = (__nv_bfloat16*)(smraw + OKH);
    __nv_bfloat16* Kl = (__nv_bfloat16*)(smraw + OKL);
    __nv_bfloat16* Vh = (__nv_bfloat16*)(smraw + OVH);
    __nv_bfloat16* Vl = (__nv_bfloat16*)(smraw + OVL);
    __nv_bfloat16* Ph = (__nv_bfloat16*)(smraw + OPH);
    __nv_bfloat16* Pl = (__nv_bfloat16*)(smraw + OPL);

    const int qb = (int)gridDim.x - 1 - (int)blockIdx.x;
    const int h = blockIdx.y, b = blockIdx.z;
    const int tid = threadIdx.x;
    const int warp = tid >> 5, lane = tid & 31;
    const int g = lane >> 2, tg = lane & 3;

    const float* Qg = g_q + ((size_t)(b * HH + h) * SS + qb * 128) * DD;
    const float* Kg = g_k + (size_t)(b * HH + h) * SS * DD;
    const float* Vg = g_v + (size_t)(b * HH + h) * SS * DD;

#pragma unroll
    for (int it = 0; it < 8; it++) {
        int f4 = tid + it * 256;
        int r = f4 >> 4, c = (f4 & 15) << 2;
        float4 v = *(const float4*)(Qg + r * 64 + c);
        uint32_t h01, h23, l01, l23;
        split2(v.x * 0.125f, v.y * 0.125f, h01, l01);
        split2(v.z * 0.125f, v.w * 0.125f, h23, l23);
        *(uint2*)&Qh[r * QP + c] = make_uint2(h01, h23);
        *(uint2*)&Ql[r * QP + c] = make_uint2(l01, l23);
    }
    __syncthreads();

    uint32_t qa_h[4][4], qa_l[4][4];
    {
        int row = warp * 16 + g;
#pragma unroll
        for (int ks = 0; ks < 4; ks++) {
            int d0 = ks * 16 + 2 * tg;
            qa_h[ks][0] = *(uint32_t*)&Qh[row * QP + d0];
            qa_h[ks][1] = *(uint32_t*)&Qh[(row + 8) * QP + d0];
            qa_h[ks][2] = *(uint32_t*)&Qh[row * QP + d0 + 8];
            qa_h[ks][3] = *(uint32_t*)&Qh[(row + 8) * QP + d0 + 8];
            qa_l[ks][0] = *(uint32_t*)&Ql[row * QP + d0];
            qa_l[ks][1] = *(uint32_t*)&Ql[(row + 8) * QP + d0];
            qa_l[ks][2] = *(uint32_t*)&Ql[row * QP + d0 + 8];
            qa_l[ks][3] = *(uint32_t*)&Ql[(row + 8) * QP + d0 + 8];
        }
    }

    float accO[8][4];
#pragma unroll
    for (int dt = 0; dt < 8; dt++)
#pragma unroll
        for (int t = 0; t < 4; t++) accO[dt][t] = 0.f;
    float l0 = 0.f, l1 = 0.f;

    const int rowL = warp * 16 + g;
    const int row0g = qb * 128 + rowL;
    const size_t wbase = (size_t)(b * HH + h) * SS * SS;
    const int nch = 2 * (qb + 1);

    for (int ch = 0; ch < nch; ch++) {
        __syncthreads();
#pragma unroll
        for (int it = 0; it < 4; it++) {
            int f4 = tid + it * 256;
            int key = f4 >> 4, c = (f4 & 15) << 2;
            float4 kv = *(const float4*)(Kg + (size_t)(ch * 64 + key) * 64 + c);
            uint32_t h01, h23, l01, l23;
            split2(kv.x, kv.y, h01, l01); split2(kv.z, kv.w, h23, l23);
            *(uint2*)&Kh[key * KP + c] = make_uint2(h01, h23);
            *(uint2*)&Kl[key * KP + c] = make_uint2(l01, l23);

            float4 vv = *(const float4*)(Vg + (size_t)(ch * 64 + key) * 64 + c);
            float vs[4] = {vv.x, vv.y, vv.z, vv.w};
#pragma unroll
            for (int j = 0; j < 4; j++) {
                __nv_bfloat16 hb = __float2bfloat16_rn(vs[j]);
                Vh[(c + j) * VP + key] = hb;
                Vl[(c + j) * VP + key] = __float2bfloat16_rn(vs[j] - __bfloat162float(hb));
            }
        }
        __syncthreads();

        const bool masked = (ch >= 2 * qb);

#pragma unroll 1
        for (int grp = 0; grp < 2; grp++) {
            float acc[4][4];
#pragma unroll
            for (int q = 0; q < 4; q++)
#pragma unroll
                for (int t = 0; t < 4; t++) acc[q][t] = 0.f;

#pragma unroll
            for (int ks = 0; ks < 4; ks++) {
                int d0 = ks * 16 + 2 * tg;
#pragma unroll
                for (int q = 0; q < 4; q++) {
                    int key = (grp * 4 + q) * 8 + g;
                    uint32_t bh[2], bl[2];
                    bh[0] = *(uint32_t*)&Kh[key * KP + d0];
                    bh[1] = *(uint32_t*)&Kh[key * KP + d0 + 8];
                    bl[0] = *(uint32_t*)&Kl[key * KP + d0];
                    bl[1] = *(uint32_t*)&Kl[key * KP + d0 + 8];
                    mma_bf16(acc[q], qa_h[ks], bh);
                    mma_bf16(acc[q], qa_h[ks], bl);
                    mma_bf16(acc[q], qa_l[ks], bh);
                }
            }

#pragma unroll
            for (int q = 0; q < 4; q++) {
                int nt = grp * 4 + q;
                int colb = ch * 64 + nt * 8 + 2 * tg;
                float e0, e1, e2, e3;
                if (masked) {
                    e0 = (colb     <= row0g)     ? __expf(acc[q][0]) : 0.f;
                    e1 = (colb + 1 <= row0g)     ? __expf(acc[q][1]) : 0.f;
                    e2 = (colb     <= row0g + 8) ? __expf(acc[q][2]) : 0.f;
                    e3 = (colb + 1 <= row0g + 8) ? __expf(acc[q][3]) : 0.f;
                } else {
                    e0 = __expf(acc[q][0]); e1 = __expf(acc[q][1]);
                    e2 = __expf(acc[q][2]); e3 = __expf(acc[q][3]);
                }
                l0 += e0 + e1; l1 += e2 + e3;
                size_t base = wbase + (size_t)row0g * SS + colb;
                *(float2*)(attn_w + base) = make_float2(e0, e1);
                *(float2*)(attn_w + base + (size_t)8 * SS) = make_float2(e2, e3);
                int pc = nt * 8 + 2 * tg;
                uint32_t ph01, pl01, ph23, pl23;
                split2(e0, e1, ph01, pl01);
                split2(e2, e3, ph23, pl23);
                *(uint32_t*)&Ph[rowL * PP + pc]       = ph01;
                *(uint32_t*)&Pl[rowL * PP + pc]       = pl01;
                *(uint32_t*)&Ph[(rowL + 8) * PP + pc] = ph23;
                *(uint32_t*)&Pl[(rowL + 8) * PP + pc] = pl23;
            }
        }
        __syncwarp();

#pragma unroll 1
        for (int ks = 0; ks < 4; ks++) {
            int k0 = ks * 16 + 2 * tg;
            uint32_t pa_h[4], pa_l[4];
            pa_h[0] = *(uint32_t*)&Ph[rowL * PP + k0];
            pa_h[1] = *(uint32_t*)&Ph[(rowL + 8) * PP + k0];
            pa_h[2] = *(uint32_t*)&Ph[rowL * PP + k0 + 8];
            pa_h[3] = *(uint32_t*)&Ph[(rowL + 8) * PP + k0 + 8];
            pa_l[0] = *(uint32_t*)&Pl[rowL * PP + k0];
            pa_l[1] = *(uint32_t*)&Pl[(rowL + 8) * PP + k0];
            pa_l[2] = *(uint32_t*)&Pl[rowL * PP + k0 + 8];
            pa_l[3] = *(uint32_t*)&Pl[(rowL + 8) * PP + k0 + 8];
#pragma unroll
            for (int dt = 0; dt < 8; dt++) {
                int d = dt * 8 + g;
                uint32_t bh[2], bl[2];
                bh[0] = *(uint32_t*)&Vh[d * VP + k0];
                bh[1] = *(uint32_t*)&Vh[d * VP + k0 + 8];
                bl[0] = *(uint32_t*)&Vl[d * VP + k0];
                bl[1] = *(uint32_t*)&Vl[d * VP + k0 + 8];
                mma_bf16(accO[dt], pa_h, bh);
                mma_bf16(accO[dt], pa_h, bl);
                mma_bf16(accO[dt], pa_l, bh);
            }
        }
    }

#pragma unroll
    for (int o = 1; o < 4; o <<= 1) {
        l0 += __shfl_xor_sync(0xffffffffu, l0, o);
        l1 += __shfl_xor_sync(0xffffffffu, l1, o);
    }
    if (tg == 0) {
        g_l[(size_t)(b * HH + h) * SS + row0g] = l0;
        g_l[(size_t)(b * HH + h) * SS + row0g + 8] = l1;
    }
    float inv0 = 1.f / l0, inv1 = 1.f / l1;

#pragma unroll
    for (int dt = 0; dt < 8; dt++) {
        int col = h * 64 + dt * 8 + 2 * tg;
        uint32_t hh, ll;
        split2(accO[dt][0] * inv0, accO[dt][1] * inv0, hh, ll);
        *(uint32_t*)&g_ctxh[(size_t)(b * SS + row0g) * EE + col] = hh;
        *(uint32_t*)&g_ctxl[(size_t)(b * SS + row0g) * EE + col] = ll;
        split2(accO[dt][2] * inv1, accO[dt][3] * inv1, hh, ll);
        *(uint32_t*)&g_ctxh[(size_t)(b * SS + row0g + 8) * EE + col] = hh;
        *(uint32_t*)&g_ctxl[(size_t)(b * SS + row0g + 8) * EE + col] = ll;
    }
}

// =================================================================================
// Kernel 3: FUSED proj GEMM + attn_w rescale — PROJ FIRST.
// Grid = 256 + NROWS. bid < 256 -> proj (all launch in wave 1, overlap with
// rescale stream); bid >= 256 -> rescale row (bid - 256). Tail = tiny rescale
// blocks, no serial proj tail.
// =================================================================================
__global__ __launch_bounds__(256, 2) void proj_rescale_fused(
    const float* __restrict__ bias, float* __restrict__ out,
    float* __restrict__ attn_w)
{
    __shared__ __nv_bfloat16 Ah[128 * AP], Al[128 * AP];
    __shared__ __nv_bfloat16 Bh[16 * BP],  Bl[16 * BP];

    const int bid = blockIdx.x;
    const int tid = threadIdx.x;

    if (bid >= 256) {
        // ---------------- rescale path (65536 rows) ----------------
        const int row = bid - 256;                 // 0..65535
        const int s = row & (SS - 1);
        const float inv = 1.f / g_l[row];
        const int lim = s + 1;
        float* p = attn_w + (size_t)row * SS;

#pragma unroll
        for (int it = 0; it < 2; it++) {
            int c = (tid + it * 256) << 2;
            float4 t;
            if (c + 3 < lim) {
                t = *(float4*)(p + c);
                t.x *= inv; t.y *= inv; t.z *= inv; t.w *= inv;
            } else if (c < lim) {
                t = *(float4*)(p + c);
                t.x = (c     < lim) ? t.x * inv : 0.f;
                t.y = (c + 1 < lim) ? t.y * inv : 0.f;
                t.z = (c + 2 < lim) ? t.z * inv : 0.f;
                t.w = (c + 3 < lim) ? t.w * inv : 0.f;
            } else {
                t = make_float4(0.f, 0.f, 0.f, 0.f);
            }
            *(float4*)(p + c) = t;
        }
        return;
    }

    // ---------------- proj path (blocks 0..255, wave 1) ----------------
    const int pbid = bid;                         // 0..255
    const int bn = pbid & 7, bm = pbid >> 3;      // 8 col-tiles x 32 row-tiles
    const int warp = tid >> 5, lane = tid & 31;
    const int g = lane >> 2, tg = lane & 3;
    const int wm = (warp >> 2) * 64, wn = (warp & 3) * 32;
    const int row0 = bm * 128, col0 = bn * 128;

    const int ar = tid >> 1, ac = (tid & 1) << 3;
    const int bk = tid >> 4, bc = (tid & 15) << 3;

    float C[4][4][4];
#pragma unroll
    for (int mi = 0; mi < 4; mi++)
#pragma unroll
        for (int ni = 0; ni < 4; ni++)
#pragma unroll
            for (int t = 0; t < 4; t++) C[mi][ni][t] = 0.f;

    for (int k0 = 0; k0 < EE; k0 += 16) {
        *(uint4*)&Ah[ar * AP + ac] = *(const uint4*)(g_ctxh + (size_t)(row0 + ar) * EE + k0 + ac);
        *(uint4*)&Al[ar * AP + ac] = *(const uint4*)(g_ctxl + (size_t)(row0 + ar) * EE + k0 + ac);
        *(uint4*)&Bh[bk * BP + bc] = *(const uint4*)(g_ph + (size_t)(k0 + bk) * EE + col0 + bc);
        *(uint4*)&Bl[bk * BP + bc] = *(const uint4*)(g_pl + (size_t)(k0 + bk) * EE + col0 + bc);
        __syncthreads();

        uint32_t a_h[4][4], a_l[4][4], b_h[4][2], b_l[4][2];
#pragma unroll
        for (int mi = 0; mi < 4; mi++) {
            int row = wm + mi * 16 + (lane & 15);
            int ko = (lane >> 4) << 3;
            ldsm4(a_h[mi][0], a_h[mi][1], a_h[mi][2], a_h[mi][3], &Ah[row * AP + ko]);
            ldsm4(a_l[mi][0], a_l[mi][1], a_l[mi][2], a_l[mi][3], &Al[row * AP + ko]);
        }
#pragma unroll
        for (int ni = 0; ni < 4; ni++) {
            int kr = (lane & 7) + (lane & 8);
            int nc = wn + ni * 8;
            ldsm2t(b_h[ni][0], b_h[ni][1], &Bh[kr * BP + nc]);
            ldsm2t(b_l[ni][0], b_l[ni][1], &Bl[kr * BP + nc]);
        }
#pragma unroll
        for (int mi = 0; mi < 4; mi++)
#pragma unroll
            for (int ni = 0; ni < 4; ni++) {
                mma_bf16(C[mi][ni], a_h[mi], b_h[ni]);
                mma_bf16(C[mi][ni], a_h[mi], b_l[ni]);
                mma_bf16(C[mi][ni], a_l[mi], b_h[ni]);
            }
        __syncthreads();
    }

#pragma unroll
    for (int mi = 0; mi < 4; mi++) {
#pragma unroll
        for (int half = 0; half < 2; half++) {
            int r = row0 + wm + mi * 16 + g + half * 8;
#pragma unroll
            for (int ni = 0; ni < 4; ni++) {
#pragma unroll
                for (int c01 = 0; c01 < 2; c01++) {
                    int n = col0 + wn + ni * 8 + 2 * tg + c01;
                    out[(size_t)r * EE + n] = C[mi][ni][half * 2 + c01] + bias[n];
                }
            }
        }
    }
}

// =================================================================================
// launch
// =================================================================================
extern "C" void kernel_launch(void* const* d_in, const int* in_sizes, int n_in,
                              void* d_out, int out_size)
{
    const float* hs = (const float*)d_in[0];
    const float* aw = (const float*)d_in[1];
    const float* ab = (const float*)d_in[2];
    const float* pw = (const float*)d_in[3];
    const float* pb = (const float*)d_in[4];

    float* out      = (float*)d_out;
    float* attn_out = out;                       // [2,2048,1024]
    float* attn_w   = out + (size_t)MM * EE;     // [2,16,2048,2048]

    cudaFuncSetAttribute(attn_kernel, cudaFuncAttributeMaxDynamicSharedMemorySize,
                         ATT_SMEM);

    __nv_bfloat16 *xh, *xl, *wh, *wl, *ph, *pl;
    cudaGetSymbolAddress((void**)&xh, g_xh); cudaGetSymbolAddress((void**)&xl, g_xl);
    cudaGetSymbolAddress((void**)&wh, g_wh); cudaGetSymbolAddress((void**)&wl, g_wl);
    cudaGetSymbolAddress((void**)&ph, g_ph); cudaGetSymbolAddress((void**)&pl, g_pl);

    split_kernel<<<(MM * EE / 4 + 255) / 256, 256>>>(hs, xh, xl, MM * EE / 4);
    split_kernel<<<(EE * NQKV / 4 + 255) / 256, 256>>>(aw, wh, wl, EE * NQKV / 4);
    split_kernel<<<(EE * EE / 4 + 255) / 256, 256>>>(pw, ph, pl, EE * EE / 4);

    qkv_gemm_bf16<<<dim3(NQKV / 128, MM / 128), 256>>>(ab);
    attn_kernel<<<dim3(SS / 128, HH, BB), 256, ATT_SMEM>>>(attn_w);
    proj_rescale_fused<<<256 + NROWS, 256>>>(pb, attn_out, attn_w);
}

// round 14
// speedup vs baseline: 1.8464x; 1.2504x over previous
#include <cuda_runtime.h>
#include <cuda_bf16.h>
#include <math.h>
#include <stdint.h>

// Problem dims
#define BB 2
#define SS 2048
#define EE 1024
#define HH 16
#define DD 64
#define MM (BB * SS)      // 4096
#define NQKV (3 * EE)     // 3072
#define NROWS (BB * HH * SS)   // 65536 attn_w rows

// ---------------- scratch ----------------
__device__ float g_q[BB * HH * SS * DD];   // [B,H,S,D]
__device__ float g_k[BB * HH * SS * DD];
__device__ float g_v[BB * HH * SS * DD];
__device__ float g_l[NROWS];               // row sums of exp(s)
// pre-split bf16 operands
__device__ __nv_bfloat16 g_xh[MM * EE],  g_xl[MM * EE];      // hidden_states
__device__ __nv_bfloat16 g_wh[EE * NQKV], g_wl[EE * NQKV];   // c_attn_w
__device__ __nv_bfloat16 g_ph[EE * EE],  g_pl[EE * EE];      // c_proj_w
__device__ __nv_bfloat16 g_ctxh[MM * EE], g_ctxl[MM * EE];   // attention context

// ---------------- bf16 helpers ----------------
__device__ __forceinline__ void mma_bf16(float* c, const uint32_t* a, const uint32_t* b) {
    asm volatile(
        "mma.sync.aligned.m16n8k16.row.col.f32.bf16.bf16.f32 "
        "{%0,%1,%2,%3}, {%4,%5,%6,%7}, {%8,%9}, {%0,%1,%2,%3};"
        : "+f"(c[0]), "+f"(c[1]), "+f"(c[2]), "+f"(c[3])
        : "r"(a[0]), "r"(a[1]), "r"(a[2]), "r"(a[3]), "r"(b[0]), "r"(b[1]));
}

__device__ __forceinline__ void ldsm4(uint32_t& r0, uint32_t& r1, uint32_t& r2, uint32_t& r3,
                                      const void* p) {
    uint32_t a = (uint32_t)__cvta_generic_to_shared(p);
    asm volatile("ldmatrix.sync.aligned.m8n8.x4.shared.b16 {%0,%1,%2,%3}, [%4];"
                 : "=r"(r0), "=r"(r1), "=r"(r2), "=r"(r3) : "r"(a));
}

__device__ __forceinline__ void ldsm2t(uint32_t& r0, uint32_t& r1, const void* p) {
    uint32_t a = (uint32_t)__cvta_generic_to_shared(p);
    asm volatile("ldmatrix.sync.aligned.m8n8.x2.trans.shared.b16 {%0,%1}, [%2];"
                 : "=r"(r0), "=r"(r1) : "r"(a));
}

__device__ __forceinline__ void split2(float a, float b, uint32_t& h, uint32_t& l) {
    __nv_bfloat162 th, tl;
    th.x = __float2bfloat16_rn(a);
    th.y = __float2bfloat16_rn(b);
    tl.x = __float2bfloat16_rn(a - __bfloat162float(th.x));
    tl.y = __float2bfloat16_rn(b - __bfloat162float(th.y));
    h = *(uint32_t*)&th;
    l = *(uint32_t*)&tl;
}

// =================================================================================
// Kernel 0: split fp32 array into bf16 hi/lo
// =================================================================================
__global__ __launch_bounds__(256) void split_kernel(
    const float* __restrict__ src, __nv_bfloat16* __restrict__ h,
    __nv_bfloat16* __restrict__ l, int n4)
{
    int i = blockIdx.x * 256 + threadIdx.x;
    if (i >= n4) return;
    float4 v = ((const float4*)src)[i];
    uint32_t h01, h23, l01, l23;
    split2(v.x, v.y, h01, l01);
    split2(v.z, v.w, h23, l23);
    *(uint2*)(h + (size_t)i * 4) = make_uint2(h01, h23);
    *(uint2*)(l + (size_t)i * 4) = make_uint2(l01, l23);
}

#define AP 24
#define BP 136

// =================================================================================
// Kernel 1: QKV GEMM, bf16 3-term, pre-split operands (R11, known good)
// =================================================================================
__global__ __launch_bounds__(256, 2) void qkv_gemm_bf16(
    const float* __restrict__ bias)
{
    __shared__ __nv_bfloat16 Ah[128 * AP], Al[128 * AP];
    __shared__ __nv_bfloat16 Bh[16 * BP],  Bl[16 * BP];

    const int bn = blockIdx.x, bm = blockIdx.y;
    const int tid = threadIdx.x;
    const int warp = tid >> 5, lane = tid & 31;
    const int g = lane >> 2, tg = lane & 3;
    const int wm = (warp >> 2) * 64, wn = (warp & 3) * 32;
    const int row0 = bm * 128, col0 = bn * 128;

    const int ar = tid >> 1, ac = (tid & 1) << 3;
    const int bk = tid >> 4, bc = (tid & 15) << 3;

    float C[4][4][4];
#pragma unroll
    for (int mi = 0; mi < 4; mi++)
#pragma unroll
        for (int ni = 0; ni < 4; ni++)
#pragma unroll
            for (int t = 0; t < 4; t++) C[mi][ni][t] = 0.f;

    for (int k0 = 0; k0 < EE; k0 += 16) {
        *(uint4*)&Ah[ar * AP + ac] = *(const uint4*)(g_xh + (size_t)(row0 + ar) * EE + k0 + ac);
        *(uint4*)&Al[ar * AP + ac] = *(const uint4*)(g_xl + (size_t)(row0 + ar) * EE + k0 + ac);
        *(uint4*)&Bh[bk * BP + bc] = *(const uint4*)(g_wh + (size_t)(k0 + bk) * NQKV + col0 + bc);
        *(uint4*)&Bl[bk * BP + bc] = *(const uint4*)(g_wl + (size_t)(k0 + bk) * NQKV + col0 + bc);
        __syncthreads();

        uint32_t a_h[4][4], a_l[4][4], b_h[4][2], b_l[4][2];
#pragma unroll
        for (int mi = 0; mi < 4; mi++) {
            int row = wm + mi * 16 + (lane & 15);
            int ko = (lane >> 4) << 3;
            ldsm4(a_h[mi][0], a_h[mi][1], a_h[mi][2], a_h[mi][3], &Ah[row * AP + ko]);
            ldsm4(a_l[mi][0], a_l[mi][1], a_l[mi][2], a_l[mi][3], &Al[row * AP + ko]);
        }
#pragma unroll
        for (int ni = 0; ni < 4; ni++) {
            int kr = (lane & 7) + (lane & 8);
            int nc = wn + ni * 8;
            ldsm2t(b_h[ni][0], b_h[ni][1], &Bh[kr * BP + nc]);
            ldsm2t(b_l[ni][0], b_l[ni][1], &Bl[kr * BP + nc]);
        }
#pragma unroll
        for (int mi = 0; mi < 4; mi++)
#pragma unroll
            for (int ni = 0; ni < 4; ni++) {
                mma_bf16(C[mi][ni], a_h[mi], b_h[ni]);
                mma_bf16(C[mi][ni], a_h[mi], b_l[ni]);
                mma_bf16(C[mi][ni], a_l[mi], b_h[ni]);
            }
        __syncthreads();
    }

#pragma unroll
    for (int mi = 0; mi < 4; mi++) {
#pragma unroll
        for (int half = 0; half < 2; half++) {
            int r = row0 + wm + mi * 16 + g + half * 8;
            int b_ = r >> 11, s = r & 2047;
#pragma unroll
            for (int ni = 0; ni < 4; ni++) {
#pragma unroll
                for (int c01 = 0; c01 < 2; c01++) {
                    int n = col0 + wn + ni * 8 + 2 * tg + c01;
                    float v = C[mi][ni][half * 2 + c01] + bias[n];
                    int which = n >> 10;
                    int e = n & 1023;
                    int hh = e >> 6, d = e & 63;
                    float* dst = (which == 0) ? g_q : (which == 1) ? g_k : g_v;
                    dst[(size_t)(((b_ * HH) + hh) * SS + s) * DD + d] = v;
                }
            }
        }
    }
}

// =================================================================================
// Kernel 2: single-pass causal attention (R8/R11 core, known good)
// =================================================================================
#define QP 72
#define KP 72
#define VP 72
#define PP 72
#define OQH 0
#define OQL (OQH + 128 * QP * 2)
#define OKH (OQL + 128 * QP * 2)
#define OKL (OKH + 64 * KP * 2)
#define OVH (OKL + 64 * KP * 2)
#define OVL (OVH + 64 * VP * 2)
#define OPH (OVL + 64 * VP * 2)
#define OPL (OPH + 128 * PP * 2)
#define ATT_SMEM (OPL + 128 * PP * 2)   // 110592

__global__ __launch_bounds__(256, 2) void attn_kernel(float* __restrict__ attn_w)
{
    extern __shared__ char smraw[];
    __nv_bfloat16* Qh = (__nv_bfloat16*)(smraw + OQH);
    __nv_bfloat16* Ql = (__nv_bfloat16*)(smraw + OQL);
    __nv_bfloat16* Kh = (__nv_bfloat16*)(smraw + OKH);
    __nv_bfloat16* Kl = (__nv_bfloat16*)(smraw + OKL);
    __nv_bfloat16* Vh = (__nv_bfloat16*)(smraw + OVH);
    __nv_bfloat16* Vl = (__nv_bfloat16*)(smraw + OVL);
    __nv_bfloat16* Ph = (__nv_bfloat16*)(smraw + OPH);
    __nv_bfloat16* Pl = (__nv_bfloat16*)(smraw + OPL);

    const int qb = (int)gridDim.x - 1 - (int)blockIdx.x;
    const int h = blockIdx.y, b = blockIdx.z;
    const int tid = threadIdx.x;
    const int warp = tid >> 5, lane = tid & 31;
    const int g = lane >> 2, tg = lane & 3;

    const float* Qg = g_q + ((size_t)(b * HH + h) * SS + qb * 128) * DD;
    const float* Kg = g_k + (size_t)(b * HH + h) * SS * DD;
    const float* Vg = g_v + (size_t)(b * HH + h) * SS * DD;

#pragma unroll
    for (int it = 0; it < 8; it++) {
        int f4 = tid + it * 256;
        int r = f4 >> 4, c = (f4 & 15) << 2;
        float4 v = *(const float4*)(Qg + r * 64 + c);
        uint32_t h01, h23, l01, l23;
        split2(v.x * 0.125f, v.y * 0.125f, h01, l01);
        split2(v.z * 0.125f, v.w * 0.125f, h23, l23);
        *(uint2*)&Qh[r * QP + c] = make_uint2(h01, h23);
        *(uint2*)&Ql[r * QP + c] = make_uint2(l01, l23);
    }
    __syncthreads();

    uint32_t qa_h[4][4], qa_l[4][4];
    {
        int row = warp * 16 + g;
#pragma unroll
        for (int ks = 0; ks < 4; ks++) {
            int d0 = ks * 16 + 2 * tg;
            qa_h[ks][0] = *(uint32_t*)&Qh[row * QP + d0];
            qa_h[ks][1] = *(uint32_t*)&Qh[(row + 8) * QP + d0];
            qa_h[ks][2] = *(uint32_t*)&Qh[row * QP + d0 + 8];
            qa_h[ks][3] = *(uint32_t*)&Qh[(row + 8) * QP + d0 + 8];
            qa_l[ks][0] = *(uint32_t*)&Ql[row * QP + d0];
            qa_l[ks][1] = *(uint32_t*)&Ql[(row + 8) * QP + d0];
            qa_l[ks][2] = *(uint32_t*)&Ql[row * QP + d0 + 8];
            qa_l[ks][3] = *(uint32_t*)&Ql[(row + 8) * QP + d0 + 8];
        }
    }

    float accO[8][4];
#pragma unroll
    for (int dt = 0; dt < 8; dt++)
#pragma unroll
        for (int t = 0; t < 4; t++) accO[dt][t] = 0.f;
    float l0 = 0.f, l1 = 0.f;

    const int rowL = warp * 16 + g;
    const int row0g = qb * 128 + rowL;
    const size_t wbase = (size_t)(b * HH + h) * SS * SS;
    const int nch = 2 * (qb + 1);

    for (int ch = 0; ch < nch; ch++) {
        __syncthreads();
#pragma unroll
        for (int it = 0; it < 4; it++) {
            int f4 = tid + it * 256;
            int key = f4 >> 4, c = (f4 & 15) << 2;
            float4 kv = *(const float4*)(Kg + (size_t)(ch * 64 + key) * 64 + c);
            uint32_t h01, h23, l01, l23;
            split2(kv.x, kv.y, h01, l01); split2(kv.z, kv.w, h23, l23);
            *(uint2*)&Kh[key * KP + c] = make_uint2(h01, h23);
            *(uint2*)&Kl[key * KP + c] = make_uint2(l01, l23);

            float4 vv = *(const float4*)(Vg + (size_t)(ch * 64 + key) * 64 + c);
            float vs[4] = {vv.x, vv.y, vv.z, vv.w};
#pragma unroll
            for (int j = 0; j < 4; j++) {
                __nv_bfloat16 hb = __float2bfloat16_rn(vs[j]);
                Vh[(c + j) * VP + key] = hb;
                Vl[(c + j) * VP + key] = __float2bfloat16_rn(vs[j] - __bfloat162float(hb));
            }
        }
        __syncthreads();

        const bool masked = (ch >= 2 * qb);

#pragma unroll 1
        for (int grp = 0; grp < 2; grp++) {
            float acc[4][4];
#pragma unroll
            for (int q = 0; q < 4; q++)
#pragma unroll
                for (int t = 0; t < 4; t++) acc[q][t] = 0.f;

#pragma unroll
            for (int ks = 0; ks < 4; ks++) {
                int d0 = ks * 16 + 2 * tg;
#pragma unroll
                for (int q = 0; q < 4; q++) {
                    int key = (grp * 4 + q) * 8 + g;
                    uint32_t bh[2], bl[2];
                    bh[0] = *(uint32_t*)&Kh[key * KP + d0];
                    bh[1] = *(uint32_t*)&Kh[key * KP + d0 + 8];
                    bl[0] = *(uint32_t*)&Kl[key * KP + d0];
                    bl[1] = *(uint32_t*)&Kl[key * KP + d0 + 8];
                    mma_bf16(acc[q], qa_h[ks], bh);
                    mma_bf16(acc[q], qa_h[ks], bl);
                    mma_bf16(acc[q], qa_l[ks], bh);
                }
            }

#pragma unroll
            for (int q = 0; q < 4; q++) {
                int nt = grp * 4 + q;
                int colb = ch * 64 + nt * 8 + 2 * tg;
                float e0, e1, e2, e3;
                if (masked) {
                    e0 = (colb     <= row0g)     ? __expf(acc[q][0]) : 0.f;
                    e1 = (colb + 1 <= row0g)     ? __expf(acc[q][1]) : 0.f;
                    e2 = (colb     <= row0g + 8) ? __expf(acc[q][2]) : 0.f;
                    e3 = (colb + 1 <= row0g + 8) ? __expf(acc[q][3]) : 0.f;
                } else {
                    e0 = __expf(acc[q][0]); e1 = __expf(acc[q][1]);
                    e2 = __expf(acc[q][2]); e3 = __expf(acc[q][3]);
                }
                l0 += e0 + e1; l1 += e2 + e3;
                size_t base = wbase + (size_t)row0g * SS + colb;
                *(float2*)(attn_w + base) = make_float2(e0, e1);
                *(float2*)(attn_w + base + (size_t)8 * SS) = make_float2(e2, e3);
                int pc = nt * 8 + 2 * tg;
                uint32_t ph01, pl01, ph23, pl23;
                split2(e0, e1, ph01, pl01);
                split2(e2, e3, ph23, pl23);
                *(uint32_t*)&Ph[rowL * PP + pc]       = ph01;
                *(uint32_t*)&Pl[rowL * PP + pc]       = pl01;
                *(uint32_t*)&Ph[(rowL + 8) * PP + pc] = ph23;
                *(uint32_t*)&Pl[(rowL + 8) * PP + pc] = pl23;
            }
        }
        __syncwarp();

#pragma unroll 1
        for (int ks = 0; ks < 4; ks++) {
            int k0 = ks * 16 + 2 * tg;
            uint32_t pa_h[4], pa_l[4];
            pa_h[0] = *(uint32_t*)&Ph[rowL * PP + k0];
            pa_h[1] = *(uint32_t*)&Ph[(rowL + 8) * PP + k0];
            pa_h[2] = *(uint32_t*)&Ph[rowL * PP + k0 + 8];
            pa_h[3] = *(uint32_t*)&Ph[(rowL + 8) * PP + k0 + 8];
            pa_l[0] = *(uint32_t*)&Pl[rowL * PP + k0];
            pa_l[1] = *(uint32_t*)&Pl[(rowL + 8) * PP + k0];
            pa_l[2] = *(uint32_t*)&Pl[rowL * PP + k0 + 8];
            pa_l[3] = *(uint32_t*)&Pl[(rowL + 8) * PP + k0 + 8];
#pragma unroll
            for (int dt = 0; dt < 8; dt++) {
                int d = dt * 8 + g;
                uint32_t bh[2], bl[2];
                bh[0] = *(uint32_t*)&Vh[d * VP + k0];
                bh[1] = *(uint32_t*)&Vh[d * VP + k0 + 8];
                bl[0] = *(uint32_t*)&Vl[d * VP + k0];
                bl[1] = *(uint32_t*)&Vl[d * VP + k0 + 8];
                mma_bf16(accO[dt], pa_h, bh);
                mma_bf16(accO[dt], pa_h, bl);
                mma_bf16(accO[dt], pa_l, bh);
            }
        }
    }

#pragma unroll
    for (int o = 1; o < 4; o <<= 1) {
        l0 += __shfl_xor_sync(0xffffffffu, l0, o);
        l1 += __shfl_xor_sync(0xffffffffu, l1, o);
    }
    if (tg == 0) {
        g_l[(size_t)(b * HH + h) * SS + row0g] = l0;
        g_l[(size_t)(b * HH + h) * SS + row0g + 8] = l1;
    }
    float inv0 = 1.f / l0, inv1 = 1.f / l1;

#pragma unroll
    for (int dt = 0; dt < 8; dt++) {
        int col = h * 64 + dt * 8 + 2 * tg;
        uint32_t hh, ll;
        split2(accO[dt][0] * inv0, accO[dt][1] * inv0, hh, ll);
        *(uint32_t*)&g_ctxh[(size_t)(b * SS + row0g) * EE + col] = hh;
        *(uint32_t*)&g_ctxl[(size_t)(b * SS + row0g) * EE + col] = ll;
        split2(accO[dt][2] * inv1, accO[dt][3] * inv1, hh, ll);
        *(uint32_t*)&g_ctxh[(size_t)(b * SS + row0g + 8) * EE + col] = hh;
        *(uint32_t*)&g_ctxl[(size_t)(b * SS + row0g + 8) * EE + col] = ll;
    }
}

// =================================================================================
// Kernel 2b: standalone rescale + zero-fill (lightweight, high occupancy — R8)
// =================================================================================
__global__ __launch_bounds__(256) void rescale_kernel(float* __restrict__ attn_w)
{
    const int row = blockIdx.x;
    const int s = row & (SS - 1);
    const float inv = 1.f / g_l[row];
    const int lim = s + 1;
    float* p = attn_w + (size_t)row * SS;

#pragma unroll
    for (int it = 0; it < 2; it++) {
        int c = (threadIdx.x + it * 256) << 2;
        float4 t;
        if (c + 3 < lim) {
            t = *(float4*)(p + c);
            t.x *= inv; t.y *= inv; t.z *= inv; t.w *= inv;
        } else if (c < lim) {
            t = *(float4*)(p + c);
            t.x = (c     < lim) ? t.x * inv : 0.f;
            t.y = (c + 1 < lim) ? t.y * inv : 0.f;
            t.z = (c + 2 < lim) ? t.z * inv : 0.f;
            t.w = (c + 3 < lim) ? t.w * inv : 0.f;
        } else {
            t = make_float4(0.f, 0.f, 0.f, 0.f);
        }
        *(float4*)(p + c) = t;
    }
}

// =================================================================================
// Kernel 3: standalone proj GEMM, bf16 3-term, pre-split operands
// =================================================================================
__global__ __launch_bounds__(256, 2) void proj_gemm_bf16(
    const float* __restrict__ bias, float* __restrict__ out)
{
    __shared__ __nv_bfloat16 Ah[128 * AP], Al[128 * AP];
    __shared__ __nv_bfloat16 Bh[16 * BP],  Bl[16 * BP];

    const int bn = blockIdx.x, bm = blockIdx.y;
    const int tid = threadIdx.x;
    const int warp = tid >> 5, lane = tid & 31;
    const int g = lane >> 2, tg = lane & 3;
    const int wm = (warp >> 2) * 64, wn = (warp & 3) * 32;
    const int row0 = bm * 128, col0 = bn * 128;

    const int ar = tid >> 1, ac = (tid & 1) << 3;
    const int bk = tid >> 4, bc = (tid & 15) << 3;

    float C[4][4][4];
#pragma unroll
    for (int mi = 0; mi < 4; mi++)
#pragma unroll
        for (int ni = 0; ni < 4; ni++)
#pragma unroll
            for (int t = 0; t < 4; t++) C[mi][ni][t] = 0.f;

    for (int k0 = 0; k0 < EE; k0 += 16) {
        *(uint4*)&Ah[ar * AP + ac] = *(const uint4*)(g_ctxh + (size_t)(row0 + ar) * EE + k0 + ac);
        *(uint4*)&Al[ar * AP + ac] = *(const uint4*)(g_ctxl + (size_t)(row0 + ar) * EE + k0 + ac);
        *(uint4*)&Bh[bk * BP + bc] = *(const uint4*)(g_ph + (size_t)(k0 + bk) * EE + col0 + bc);
        *(uint4*)&Bl[bk * BP + bc] = *(const uint4*)(g_pl + (size_t)(k0 + bk) * EE + col0 + bc);
        __syncthreads();

        uint32_t a_h[4][4], a_l[4][4], b_h[4][2], b_l[4][2];
#pragma unroll
        for (int mi = 0; mi < 4; mi++) {
            int row = wm + mi * 16 + (lane & 15);
            int ko = (lane >> 4) << 3;
            ldsm4(a_h[mi][0], a_h[mi][1], a_h[mi][2], a_h[mi][3], &Ah[row * AP + ko]);
            ldsm4(a_l[mi][0], a_l[mi][1], a_l[mi][2], a_l[mi][3], &Al[row * AP + ko]);
        }
#pragma unroll
        for (int ni = 0; ni < 4; ni++) {
            int kr = (lane & 7) + (lane & 8);
            int nc = wn + ni * 8;
            ldsm2t(b_h[ni][0], b_h[ni][1], &Bh[kr * BP + nc]);
            ldsm2t(b_l[ni][0], b_l[ni][1], &Bl[kr * BP + nc]);
        }
#pragma unroll
        for (int mi = 0; mi < 4; mi++)
#pragma unroll
            for (int ni = 0; ni < 4; ni++) {
                mma_bf16(C[mi][ni], a_h[mi], b_h[ni]);
                mma_bf16(C[mi][ni], a_h[mi], b_l[ni]);
                mma_bf16(C[mi][ni], a_l[mi], b_h[ni]);
            }
        __syncthreads();
    }

#pragma unroll
    for (int mi = 0; mi < 4; mi++) {
#pragma unroll
        for (int half = 0; half < 2; half++) {
            int r = row0 + wm + mi * 16 + g + half * 8;
#pragma unroll
            for (int ni = 0; ni < 4; ni++) {
#pragma unroll
                for (int c01 = 0; c01 < 2; c01++) {
                    int n = col0 + wn + ni * 8 + 2 * tg + c01;
                    out[(size_t)r * EE + n] = C[mi][ni][half * 2 + c01] + bias[n];
                }
            }
        }
    }
}

// =================================================================================
// launch
// =================================================================================
extern "C" void kernel_launch(void* const* d_in, const int* in_sizes, int n_in,
                              void* d_out, int out_size)
{
    const float* hs = (const float*)d_in[0];
    const float* aw = (const float*)d_in[1];
    const float* ab = (const float*)d_in[2];
    const float* pw = (const float*)d_in[3];
    const float* pb = (const float*)d_in[4];

    float* out      = (float*)d_out;
    float* attn_out = out;                       // [2,2048,1024]
    float* attn_w   = out + (size_t)MM * EE;     // [2,16,2048,2048]

    cudaFuncSetAttribute(attn_kernel, cudaFuncAttributeMaxDynamicSharedMemorySize,
                         ATT_SMEM);

    __nv_bfloat16 *xh, *xl, *wh, *wl, *ph, *pl;
    cudaGetSymbolAddress((void**)&xh, g_xh); cudaGetSymbolAddress((void**)&xl, g_xl);
    cudaGetSymbolAddress((void**)&wh, g_wh); cudaGetSymbolAddress((void**)&wl, g_wl);
    cudaGetSymbolAddress((void**)&ph, g_ph); cudaGetSymbolAddress((void**)&pl, g_pl);

    split_kernel<<<(MM * EE / 4 + 255) / 256, 256>>>(hs, xh, xl, MM * EE / 4);
    split_kernel<<<(EE * NQKV / 4 + 255) / 256, 256>>>(aw, wh, wl, EE * NQKV / 4);
    split_kernel<<<(EE * EE / 4 + 255) / 256, 256>>>(pw, ph, pl, EE * EE / 4);

    qkv_gemm_bf16<<<dim3(NQKV / 128, MM / 128), 256>>>(ab);
    attn_kernel<<<dim3(SS / 128, HH, BB), 256, ATT_SMEM>>>(attn_w);
    rescale_kernel<<<NROWS, 256>>>(attn_w);
    proj_gemm_bf16<<<dim3(EE / 128, MM / 128), 256>>>(pb, attn_out);
}